// round 15
// baseline (speedup 1.0000x reference)
#include <cuda_runtime.h>
#include <cuda_fp16.h>
#include <cstdint>
#include <cstddef>

// ---- problem shapes ----
#define MM 8192
#define NN 11008
#define KK 4096
#define GG 32

// ---- GEMM: 128x128 CTA, 8 warps of 32x64, BK=64 three-stage, 2 CTAs/SM ----
#define BM 128
#define BN 128
#define KP 64                       // stages of BK=64
#define THREADS 256

#define NB (NN / BN)                // 86
#define MB (MM / BM)                // 64
#define NTILES (MB * NB)            // 5504

#define A_HALVES 4096               // per (mb,kt32): 8 KB
#define A_KT_BYTES (A_HALVES * 2)
#define B_HALVES 4096               // per (nb,kt32): 8 KB (16 nt-tiles)
#define B_KT_BYTES (B_HALVES * 2)

// stage: [A kt0 8K][A kt1 8K][B kt0 8K][B kt1 8K] = 32 KB
#define STAGE_A_BYTES (2 * A_KT_BYTES)                 // 16384
#define STAGE_BYTES   (STAGE_A_BYTES + 2 * B_KT_BYTES) // 32768
#define SMEM_TOTAL    (3 * STAGE_BYTES)                // 98304 -> 2 CTAs/SM

#define XTILES (MB * 128 * 2 * 8)   // 131072
#define WTILES (NB * 128 * 2 * 16)  // 352256

// ---- scratch ----
__device__ __align__(256) __half g_Xa[(size_t)MM * KK];
__device__ __align__(256) __half g_Wb[(size_t)NN * KK];

// ---------------- helpers ----------------
__device__ __forceinline__ void cp16(uint32_t s, const void* g) {
    asm volatile("cp.async.cg.shared.global [%0], [%1], 16;" :: "r"(s), "l"(g));
}
__device__ __forceinline__ uint32_t smem_u32(const void* p) {
    uint32_t a;
    asm("{ .reg .u64 t; cvta.to.shared.u64 t, %1; cvt.u32.u64 %0, t; }"
        : "=r"(a) : "l"(p));
    return a;
}
__device__ __forceinline__ void cp_commit() {
    asm volatile("cp.async.commit_group;" ::: "memory");
}
__device__ __forceinline__ void cp_wait1() {
    asm volatile("cp.async.wait_group 1;" ::: "memory");
}
__device__ __forceinline__ void cp_wait0() {
    asm volatile("cp.async.wait_group 0;" ::: "memory");
}
__device__ __forceinline__ void mma_f16(float* c, const uint32_t* a, const uint32_t* b) {
    asm volatile(
        "mma.sync.aligned.m16n8k16.row.col.f32.f16.f16.f32 "
        "{%0,%1,%2,%3}, {%4,%5,%6,%7}, {%8,%9}, {%0,%1,%2,%3};\n"
        : "+f"(c[0]), "+f"(c[1]), "+f"(c[2]), "+f"(c[3])
        : "r"(a[0]), "r"(a[1]), "r"(a[2]), "r"(a[3]),
          "r"(b[0]), "r"(b[1]));
}
__device__ __forceinline__ uint32_t pack2(float x, float y) {
    __half2 h = __floats2half2_rn(x, y);
    return *reinterpret_cast<uint32_t*>(&h);
}

// ---------------- merged prepass (X tiles, then W tiles; unroll-2) ----------------
__global__ void prep_all(const float* __restrict__ X, const float* __restrict__ SX,
                         const float* __restrict__ W, const float* __restrict__ WS,
                         const float* __restrict__ OFF) {
    const int lane = threadIdx.x & 31;
    const int gw = (blockIdx.x * blockDim.x + threadIdx.x) >> 5;
    const int nw = (gridDim.x * blockDim.x) >> 5;

    auto do_x = [&](int t) {
        const int mt  = t & 7;
        const int kt2 = (t >> 3) & 1;
        const int kt  = (t >> 4) & 127;
        const int mb  = t >> 11;
        const int r = mb * BM + mt * 16 + (lane >> 2);
        const int k = kt * 32 + kt2 * 16 + (lane & 3) * 2;
        const float s0 = __ldg(SX + r);
        const float s1 = __ldg(SX + r + 8);
        const float2 x00 = *reinterpret_cast<const float2*>(X + (size_t)r * KK + k);
        const float2 x10 = *reinterpret_cast<const float2*>(X + (size_t)(r + 8) * KK + k);
        const float2 x01 = *reinterpret_cast<const float2*>(X + (size_t)r * KK + k + 8);
        const float2 x11 = *reinterpret_cast<const float2*>(X + (size_t)(r + 8) * KK + k + 8);
        uint4 v;
        v.x = pack2(x00.x * s0, x00.y * s0);
        v.y = pack2(x10.x * s1, x10.y * s1);
        v.z = pack2(x01.x * s0, x01.y * s0);
        v.w = pack2(x11.x * s1, x11.y * s1);
        *reinterpret_cast<uint4*>(g_Xa + (size_t)t * 256 + lane * 8) = v;
    };

    // u = ((nb*128 + kt)*2 + kt2)*16 + nt ; 8x16 tile; lane holds uint2 at u*128 + lane*4
    auto do_w = [&](int u) {
        const int nt  = u & 15;
        const int kt2 = (u >> 4) & 1;
        const int kt  = (u >> 5) & 127;
        const int nb  = u >> 12;
        const int n = nb * BN + nt * 8 + (lane >> 2);
        const int k = kt * 32 + kt2 * 16 + (lane & 3) * 2;
        const int g = kt >> 2;
        const float ws  = __ldg(WS + (size_t)n * GG + g);
        const float off = __ldg(OFF + (size_t)n * GG + g);
        const float2 w0 = *reinterpret_cast<const float2*>(W + (size_t)n * KK + k);
        const float2 w1 = *reinterpret_cast<const float2*>(W + (size_t)n * KK + k + 8);
        uint2 v;
        v.x = pack2((w0.x - off) * ws, (w0.y - off) * ws);
        v.y = pack2((w1.x - off) * ws, (w1.y - off) * ws);
        *reinterpret_cast<uint2*>(g_Wb + (size_t)u * 128 + lane * 4) = v;
    };

    const int total = XTILES + WTILES;
    int t = gw * 2;
    const int stride = nw * 2;
    for (; t + 1 < total; t += stride) {
        if (t < XTILES) do_x(t); else do_w(t - XTILES);
        if (t + 1 < XTILES) do_x(t + 1); else do_w(t + 1 - XTILES);
    }
    if (t < total) {
        if (t < XTILES) do_x(t); else do_w(t - XTILES);
    }
}

// ---------------- GEMM: 8 warps of 32x64, 3-stage BK=64, 2 CTAs/SM ----------------
__global__ __launch_bounds__(THREADS, 2)
void gemm_frag(float* __restrict__ OUT) {
    extern __shared__ char smem[];
    const uint32_t sbase = smem_u32(smem);

    const int tid = threadIdx.x;
    const int wid = tid >> 5;       // 0..7
    const int lane = tid & 31;
    const int wm = wid >> 1;        // 0..3  (m quarter: 32 rows)
    const int wn = wid & 1;         // 0..1  (n half: 64 cols)

    // CTA swizzle: groups of 8 mb per nb sweep.
    const int bid = blockIdx.x;
    const int grp = bid / (8 * NB);
    const int rem = bid - grp * (8 * NB);
    const int mb = grp * 8 + (rem & 7);
    const int nb = rem >> 3;

    const __half* Ag = g_Xa + (size_t)mb * 128 * A_HALVES;
    const __half* Bg = g_Wb + (size_t)nb * 128 * B_HALVES;

    float acc[2][8][4];
    #pragma unroll
    for (int i = 0; i < 2; i++)
        #pragma unroll
        for (int j = 0; j < 8; j++)
            #pragma unroll
            for (int c = 0; c < 4; c++) acc[i][j][c] = 0.f;

    // stage holds kt32 pair {2t, 2t+1}; 32KB / 256 thr = 128B/thread
    auto load_stage = [&](int buf, int t) {
        const uint32_t st = sbase + buf * STAGE_BYTES;
        #pragma unroll
        for (int h = 0; h < 2; h++) {
            const char* a = (const char*)(Ag + (size_t)(2 * t + h) * A_HALVES) + tid * 32;
            const uint32_t sa = st + h * A_KT_BYTES + tid * 32;
            cp16(sa, a);
            cp16(sa + 16, a + 16);
            const char* b = (const char*)(Bg + (size_t)(2 * t + h) * B_HALVES) + tid * 32;
            const uint32_t sb2 = st + STAGE_A_BYTES + h * B_KT_BYTES + tid * 32;
            cp16(sb2, b);
            cp16(sb2 + 16, b + 16);
        }
        cp_commit();
    };

    auto compute = [&](int buf) {
        const char* stg = smem + buf * STAGE_BYTES;
        #pragma unroll
        for (int h = 0; h < 2; h++) {
            const char* As = stg + h * A_KT_BYTES;
            const char* Bs = stg + STAGE_A_BYTES + h * B_KT_BYTES;
            #pragma unroll
            for (int kt2 = 0; kt2 < 2; kt2++) {
                uint4 af[2];
                #pragma unroll
                for (int mi = 0; mi < 2; mi++) {
                    const int mt = wm * 2 + mi;
                    af[mi] = *reinterpret_cast<const uint4*>(
                        As + (kt2 * 8 + mt) * 512 + lane * 16);
                }
                uint2 bf[8];
                #pragma unroll
                for (int ni = 0; ni < 8; ni++) {
                    const int nt = wn * 8 + ni;
                    bf[ni] = *reinterpret_cast<const uint2*>(
                        Bs + (kt2 * 16 + nt) * 256 + lane * 8);
                }
                #pragma unroll
                for (int mi = 0; mi < 2; mi++)
                    #pragma unroll
                    for (int ni = 0; ni < 8; ni++)
                        mma_f16(acc[mi][ni],
                                reinterpret_cast<const uint32_t*>(&af[mi]),
                                reinterpret_cast<const uint32_t*>(&bf[ni]));
            }
        }
    };

    // 3-stage pipeline: wait1 -> sync -> load(t+2) -> compute(t)
    load_stage(0, 0);
    load_stage(1, 1);
    #pragma unroll 1
    for (int t = 0; t < KP; t++) {
        if (t < KP - 1) cp_wait1(); else cp_wait0();
        __syncthreads();
        if (t + 2 < KP) load_stage((t + 2) % 3, t + 2);
        compute(t % 3);
    }

    // epilogue
    const int m0 = mb * BM + wm * 32;
    const int n0 = nb * BN + wn * 64;
    #pragma unroll
    for (int mi = 0; mi < 2; mi++) {
        const int row = m0 + mi * 16 + (lane >> 2);
        #pragma unroll
        for (int ni = 0; ni < 8; ni++) {
            const int col = n0 + ni * 8 + (lane & 3) * 2;
            float2 v0, v1;
            v0.x = acc[mi][ni][0]; v0.y = acc[mi][ni][1];
            v1.x = acc[mi][ni][2]; v1.y = acc[mi][ni][3];
            *reinterpret_cast<float2*>(OUT + (size_t)row * NN + col)       = v0;
            *reinterpret_cast<float2*>(OUT + (size_t)(row + 8) * NN + col) = v1;
        }
    }
}

// ---------------- launch ----------------
extern "C" void kernel_launch(void* const* d_in, const int* in_sizes, int n_in,
                              void* d_out, int out_size) {
    const float* X   = (const float*)d_in[0];
    const float* SX  = (const float*)d_in[1];
    const float* W   = (const float*)d_in[2];
    const float* WS  = (const float*)d_in[3];
    const float* OFF = (const float*)d_in[4];
    float* OUT = (float*)d_out;

    cudaFuncSetAttribute(gemm_frag,
                         cudaFuncAttributeMaxDynamicSharedMemorySize, SMEM_TOTAL);

    prep_all<<<2048, 256>>>(X, SX, W, WS, OFF);

    gemm_frag<<<NTILES, THREADS, SMEM_TOTAL>>>(OUT);
}

// round 16
// speedup vs baseline: 1.6113x; 1.6113x over previous
#include <cuda_runtime.h>
#include <cuda_fp16.h>
#include <cstdint>
#include <cstddef>

// ---- problem shapes ----
#define MM 8192
#define NN 11008
#define KK 4096
#define GG 32

// ---- GEMM tiling: 128x256 CTA, 16 warps of 64x32, BK=128 two-stage, persistent ----
#define BM 128
#define BN 256
#define KP 32                       // 32 stages of BK=128
#define THREADS 512

#define NB (NN / BN)                // 43
#define MB (MM / BM)                // 64
#define NTILES (MB * NB)            // 2752
#define GRID 148

#define A_HALVES 4096               // per (mb,kt32): 8 KB
#define A_KT_BYTES (A_HALVES * 2)
#define B_HALVES 8192               // per (nb,kt32): 16 KB
#define B_KT_BYTES (B_HALVES * 2)

#define STAGE_A_BYTES (4 * A_KT_BYTES)                 // 32768
#define STAGE_BYTES   (STAGE_A_BYTES + 4 * B_KT_BYTES) // 98304
#define SMEM_TOTAL    (2 * STAGE_BYTES)                // 196608

#define XTILES (MB * 128 * 2 * 8)   // 131072
#define WTILES (NB * 128 * 2 * 32)  // 352256

// ---- scratch ----
__device__ __align__(256) __half g_Xa[(size_t)MM * KK];
__device__ __align__(256) __half g_Wb[(size_t)NN * KK];

// ---------------- helpers ----------------
__device__ __forceinline__ void cp16(uint32_t s, const void* g) {
    asm volatile("cp.async.cg.shared.global [%0], [%1], 16;" :: "r"(s), "l"(g));
}
__device__ __forceinline__ uint32_t smem_u32(const void* p) {
    uint32_t a;
    asm("{ .reg .u64 t; cvta.to.shared.u64 t, %1; cvt.u32.u64 %0, t; }"
        : "=r"(a) : "l"(p));
    return a;
}
__device__ __forceinline__ void cp_commit() {
    asm volatile("cp.async.commit_group;" ::: "memory");
}
__device__ __forceinline__ void cp_wait0() {
    asm volatile("cp.async.wait_group 0;" ::: "memory");
}
__device__ __forceinline__ void mma_f16(float* c, const uint32_t* a, const uint32_t* b) {
    asm volatile(
        "mma.sync.aligned.m16n8k16.row.col.f32.f16.f16.f32 "
        "{%0,%1,%2,%3}, {%4,%5,%6,%7}, {%8,%9}, {%0,%1,%2,%3};\n"
        : "+f"(c[0]), "+f"(c[1]), "+f"(c[2]), "+f"(c[3])
        : "r"(a[0]), "r"(a[1]), "r"(a[2]), "r"(a[3]),
          "r"(b[0]), "r"(b[1]));
}
__device__ __forceinline__ uint32_t pack2(float x, float y) {
    __half2 h = __floats2half2_rn(x, y);
    return *reinterpret_cast<uint32_t*>(&h);
}

// ---------------- merged prepass (X tiles, then W tiles; unroll-2) ----------------
__global__ void prep_all(const float* __restrict__ X, const float* __restrict__ SX,
                         const float* __restrict__ W, const float* __restrict__ WS,
                         const float* __restrict__ OFF) {
    const int lane = threadIdx.x & 31;
    const int gw = (blockIdx.x * blockDim.x + threadIdx.x) >> 5;
    const int nw = (gridDim.x * blockDim.x) >> 5;

    auto do_x = [&](int t) {
        const int mt  = t & 7;
        const int kt2 = (t >> 3) & 1;
        const int kt  = (t >> 4) & 127;
        const int mb  = t >> 11;
        const int r = mb * BM + mt * 16 + (lane >> 2);
        const int k = kt * 32 + kt2 * 16 + (lane & 3) * 2;
        const float s0 = __ldg(SX + r);
        const float s1 = __ldg(SX + r + 8);
        const float2 x00 = *reinterpret_cast<const float2*>(X + (size_t)r * KK + k);
        const float2 x10 = *reinterpret_cast<const float2*>(X + (size_t)(r + 8) * KK + k);
        const float2 x01 = *reinterpret_cast<const float2*>(X + (size_t)r * KK + k + 8);
        const float2 x11 = *reinterpret_cast<const float2*>(X + (size_t)(r + 8) * KK + k + 8);
        uint4 v;
        v.x = pack2(x00.x * s0, x00.y * s0);
        v.y = pack2(x10.x * s1, x10.y * s1);
        v.z = pack2(x01.x * s0, x01.y * s0);
        v.w = pack2(x11.x * s1, x11.y * s1);
        *reinterpret_cast<uint4*>(g_Xa + (size_t)t * 256 + lane * 8) = v;
    };

    auto do_w = [&](int u) {
        const int nt  = u & 31;
        const int kt2 = (u >> 5) & 1;
        const int kt  = (u >> 6) & 127;
        const int nb  = u >> 13;
        const int n = nb * BN + nt * 8 + (lane >> 2);
        const int k = kt * 32 + kt2 * 16 + (lane & 3) * 2;
        const int g = kt >> 2;
        const float ws  = __ldg(WS + (size_t)n * GG + g);
        const float off = __ldg(OFF + (size_t)n * GG + g);
        const float2 w0 = *reinterpret_cast<const float2*>(W + (size_t)n * KK + k);
        const float2 w1 = *reinterpret_cast<const float2*>(W + (size_t)n * KK + k + 8);
        uint2 v;
        v.x = pack2((w0.x - off) * ws, (w0.y - off) * ws);
        v.y = pack2((w1.x - off) * ws, (w1.y - off) * ws);
        *reinterpret_cast<uint2*>(g_Wb + (size_t)u * 128 + lane * 4) = v;
    };

    const int total = XTILES + WTILES;
    int t = gw * 2;
    const int stride = nw * 2;
    for (; t + 1 < total; t += stride) {
        if (t < XTILES) do_x(t); else do_w(t - XTILES);
        if (t + 1 < XTILES) do_x(t + 1); else do_w(t + 1 - XTILES);
    }
    if (t < total) {
        if (t < XTILES) do_x(t); else do_w(t - XTILES);
    }
}

// ---------------- persistent GEMM: 16 warps of 64x32 ----------------
__global__ __launch_bounds__(THREADS, 1)
void gemm_persist(float* __restrict__ OUT) {
    extern __shared__ char smem[];
    const uint32_t sbase = smem_u32(smem);

    const int tid = threadIdx.x;
    const int wid = tid >> 5;       // 0..15
    const int lane = tid & 31;
    const int wm = wid >> 3;        // 0..1  (m half)
    const int wn = wid & 7;         // 0..7  (n eighth)

    auto tile_coords = [&](int tile, int& mb, int& nb) {
        const int grp = tile / (8 * NB);
        const int rem = tile - grp * (8 * NB);
        mb = grp * 8 + (rem & 7);
        nb = rem >> 3;
    };

    auto load_stage = [&](int buf, const __half* Ag, const __half* Bg, int t) {
        const uint32_t st = sbase + buf * STAGE_BYTES;
        #pragma unroll
        for (int h = 0; h < 4; h++) {
            const char* a = (const char*)(Ag + (size_t)(4 * t + h) * A_HALVES) + tid * 16;
            cp16(st + h * A_KT_BYTES + tid * 16, a);
            const char* b = (const char*)(Bg + (size_t)(4 * t + h) * B_HALVES) + tid * 32;
            const uint32_t sb2 = st + STAGE_A_BYTES + h * B_KT_BYTES + tid * 32;
            cp16(sb2, b);
            cp16(sb2 + 16, b + 16);
        }
        cp_commit();
    };

    float acc[4][4][4];

    auto compute = [&](int buf) {
        const char* stg = smem + buf * STAGE_BYTES;
        #pragma unroll
        for (int h = 0; h < 4; h++) {
            const char* As = stg + h * A_KT_BYTES;
            const char* Bs = stg + STAGE_A_BYTES + h * B_KT_BYTES;
            #pragma unroll
            for (int kt2 = 0; kt2 < 2; kt2++) {
                uint4 af[4];
                #pragma unroll
                for (int mi = 0; mi < 4; mi++) {
                    const int mt = wm * 4 + mi;
                    af[mi] = *reinterpret_cast<const uint4*>(
                        As + (kt2 * 8 + mt) * 512 + lane * 16);
                }
                uint2 bf[4];
                #pragma unroll
                for (int ni = 0; ni < 4; ni++) {
                    const int nt = wn * 4 + ni;
                    bf[ni] = *reinterpret_cast<const uint2*>(
                        Bs + (kt2 * 32 + nt) * 256 + lane * 8);
                }
                #pragma unroll
                for (int mi = 0; mi < 4; mi++)
                    #pragma unroll
                    for (int ni = 0; ni < 4; ni++)
                        mma_f16(acc[mi][ni],
                                reinterpret_cast<const uint32_t*>(&af[mi]),
                                reinterpret_cast<const uint32_t*>(&bf[ni]));
            }
        }
    };

    int tile = blockIdx.x;
    if (tile >= NTILES) return;

    int mb, nb;
    tile_coords(tile, mb, nb);
    const __half* Ag = g_Xa + (size_t)mb * 128 * A_HALVES;
    const __half* Bg = g_Wb + (size_t)nb * 128 * B_HALVES;
    const __half* AgN = Ag;
    const __half* BgN = Bg;
    int mbN = mb, nbN = nb;

    int buf = 0;
    load_stage(buf, Ag, Bg, 0);

    while (true) {
        #pragma unroll
        for (int i = 0; i < 4; i++)
            #pragma unroll
            for (int j = 0; j < 4; j++)
                #pragma unroll
                for (int c = 0; c < 4; c++) acc[i][j][c] = 0.f;

        #pragma unroll 1
        for (int t = 0; t < KP; t++) {
            cp_wait0();              // copies for current stage landed
            __syncthreads();         // all visible; previous compute done
            if (t + 1 < KP) {
                load_stage(buf ^ 1, Ag, Bg, t + 1);
            } else {
                const int ntile = tile + GRID;
                if (ntile < NTILES) {
                    tile_coords(ntile, mbN, nbN);
                    AgN = g_Xa + (size_t)mbN * 128 * A_HALVES;
                    BgN = g_Wb + (size_t)nbN * 128 * B_HALVES;
                    load_stage(buf ^ 1, AgN, BgN, 0);   // cross-tile prefetch
                }
            }
            compute(buf);
            buf ^= 1;
        }

        // epilogue: overlaps in-flight cross-tile prefetch
        const int m0 = mb * BM + wm * 64;
        const int n0 = nb * BN + wn * 32;
        #pragma unroll
        for (int mi = 0; mi < 4; mi++) {
            const int row = m0 + mi * 16 + (lane >> 2);
            #pragma unroll
            for (int ni = 0; ni < 4; ni++) {
                const int col = n0 + ni * 8 + (lane & 3) * 2;
                float2 v0, v1;
                v0.x = acc[mi][ni][0]; v0.y = acc[mi][ni][1];
                v1.x = acc[mi][ni][2]; v1.y = acc[mi][ni][3];
                *reinterpret_cast<float2*>(OUT + (size_t)row * NN + col)       = v0;
                *reinterpret_cast<float2*>(OUT + (size_t)(row + 8) * NN + col) = v1;
            }
        }

        tile += GRID;
        if (tile >= NTILES) break;
        mb = mbN; nb = nbN; Ag = AgN; Bg = BgN;
    }
}

// ---------------- launch ----------------
extern "C" void kernel_launch(void* const* d_in, const int* in_sizes, int n_in,
                              void* d_out, int out_size) {
    const float* X   = (const float*)d_in[0];
    const float* SX  = (const float*)d_in[1];
    const float* W   = (const float*)d_in[2];
    const float* WS  = (const float*)d_in[3];
    const float* OFF = (const float*)d_in[4];
    float* OUT = (float*)d_out;

    cudaFuncSetAttribute(gemm_persist,
                         cudaFuncAttributeMaxDynamicSharedMemorySize, SMEM_TOTAL);

    prep_all<<<2048, 256>>>(X, SX, W, WS, OFF);

    gemm_persist<<<GRID, THREADS, SMEM_TOTAL>>>(OUT);
}

// round 17
// speedup vs baseline: 1.7251x; 1.0706x over previous
#include <cuda_runtime.h>
#include <cuda_fp16.h>
#include <cstdint>
#include <cstddef>

// ---- problem shapes ----
#define MM 8192
#define NN 11008
#define KK 4096
#define GG 32

// ---- GEMM tiling: 128x256 CTA, 16 warps of 64x32, BK=128 two-stage, persistent,
// ---- mbarrier free-running pipeline (no mainloop __syncthreads) ----
#define BM 128
#define BN 256
#define KP 32                       // 32 stages of BK=128
#define THREADS 512

#define NB (NN / BN)                // 43
#define MB (MM / BM)                // 64
#define NTILES (MB * NB)            // 2752
#define GRID 148

#define A_HALVES 4096               // per (mb,kt32): 8 KB
#define A_KT_BYTES (A_HALVES * 2)
#define B_HALVES 8192               // per (nb,kt32): 16 KB
#define B_KT_BYTES (B_HALVES * 2)

#define STAGE_A_BYTES (4 * A_KT_BYTES)                 // 32768
#define STAGE_BYTES   (STAGE_A_BYTES + 4 * B_KT_BYTES) // 98304
#define SMEM_HDR      1024
#define SMEM_TOTAL    (SMEM_HDR + 2 * STAGE_BYTES)     // 197632

// mbarrier offsets in header: full0, full1, empty0, empty1
#define MB_FULL(b)  (0 + 8 * (b))
#define MB_EMPTY(b) (16 + 8 * (b))

#define XTILES (MB * 128 * 2 * 8)   // 131072
#define WTILES (NB * 128 * 2 * 32)  // 352256

// ---- scratch ----
__device__ __align__(256) __half g_Xa[(size_t)MM * KK];
__device__ __align__(256) __half g_Wb[(size_t)NN * KK];

// ---------------- helpers ----------------
__device__ __forceinline__ void cp16(uint32_t s, const void* g) {
    asm volatile("cp.async.cg.shared.global [%0], [%1], 16;" :: "r"(s), "l"(g));
}
__device__ __forceinline__ uint32_t smem_u32(const void* p) {
    uint32_t a;
    asm("{ .reg .u64 t; cvta.to.shared.u64 t, %1; cvt.u32.u64 %0, t; }"
        : "=r"(a) : "l"(p));
    return a;
}
__device__ __forceinline__ void mbar_init(uint32_t a, uint32_t cnt) {
    asm volatile("mbarrier.init.shared.b64 [%0], %1;" :: "r"(a), "r"(cnt) : "memory");
}
// arrive on mbarrier when ALL of this thread's prior cp.asyncs have completed
__device__ __forceinline__ void cp_mbar_arrive(uint32_t a) {
    asm volatile("cp.async.mbarrier.arrive.noinc.shared::cta.b64 [%0];"
                 :: "r"(a) : "memory");
}
__device__ __forceinline__ void mbar_arrive(uint32_t a) {
    asm volatile("mbarrier.arrive.shared.b64 _, [%0];" :: "r"(a) : "memory");
}
__device__ __forceinline__ void mbar_wait(uint32_t a, uint32_t parity) {
    asm volatile(
        "{\n\t.reg .pred P;\n"
        "W_%=:\n\t"
        "mbarrier.try_wait.parity.acquire.cta.shared::cta.b64 P, [%0], %1, 0x989680;\n\t"
        "@P bra.uni D_%=;\n\t"
        "bra.uni W_%=;\n"
        "D_%=:\n\t}"
        :: "r"(a), "r"(parity) : "memory");
}
__device__ __forceinline__ void mma_f16(float* c, const uint32_t* a, const uint32_t* b) {
    asm volatile(
        "mma.sync.aligned.m16n8k16.row.col.f32.f16.f16.f32 "
        "{%0,%1,%2,%3}, {%4,%5,%6,%7}, {%8,%9}, {%0,%1,%2,%3};\n"
        : "+f"(c[0]), "+f"(c[1]), "+f"(c[2]), "+f"(c[3])
        : "r"(a[0]), "r"(a[1]), "r"(a[2]), "r"(a[3]),
          "r"(b[0]), "r"(b[1]));
}
__device__ __forceinline__ uint32_t pack2(float x, float y) {
    __half2 h = __floats2half2_rn(x, y);
    return *reinterpret_cast<uint32_t*>(&h);
}

// ---------------- merged prepass (X tiles, then W tiles; unroll-2) ----------------
__global__ void prep_all(const float* __restrict__ X, const float* __restrict__ SX,
                         const float* __restrict__ W, const float* __restrict__ WS,
                         const float* __restrict__ OFF) {
    const int lane = threadIdx.x & 31;
    const int gw = (blockIdx.x * blockDim.x + threadIdx.x) >> 5;
    const int nw = (gridDim.x * blockDim.x) >> 5;

    auto do_x = [&](int t) {
        const int mt  = t & 7;
        const int kt2 = (t >> 3) & 1;
        const int kt  = (t >> 4) & 127;
        const int mb  = t >> 11;
        const int r = mb * BM + mt * 16 + (lane >> 2);
        const int k = kt * 32 + kt2 * 16 + (lane & 3) * 2;
        const float s0 = __ldg(SX + r);
        const float s1 = __ldg(SX + r + 8);
        const float2 x00 = *reinterpret_cast<const float2*>(X + (size_t)r * KK + k);
        const float2 x10 = *reinterpret_cast<const float2*>(X + (size_t)(r + 8) * KK + k);
        const float2 x01 = *reinterpret_cast<const float2*>(X + (size_t)r * KK + k + 8);
        const float2 x11 = *reinterpret_cast<const float2*>(X + (size_t)(r + 8) * KK + k + 8);
        uint4 v;
        v.x = pack2(x00.x * s0, x00.y * s0);
        v.y = pack2(x10.x * s1, x10.y * s1);
        v.z = pack2(x01.x * s0, x01.y * s0);
        v.w = pack2(x11.x * s1, x11.y * s1);
        *reinterpret_cast<uint4*>(g_Xa + (size_t)t * 256 + lane * 8) = v;
    };

    auto do_w = [&](int u) {
        const int nt  = u & 31;
        const int kt2 = (u >> 5) & 1;
        const int kt  = (u >> 6) & 127;
        const int nb  = u >> 13;
        const int n = nb * BN + nt * 8 + (lane >> 2);
        const int k = kt * 32 + kt2 * 16 + (lane & 3) * 2;
        const int g = kt >> 2;
        const float ws  = __ldg(WS + (size_t)n * GG + g);
        const float off = __ldg(OFF + (size_t)n * GG + g);
        const float2 w0 = *reinterpret_cast<const float2*>(W + (size_t)n * KK + k);
        const float2 w1 = *reinterpret_cast<const float2*>(W + (size_t)n * KK + k + 8);
        uint2 v;
        v.x = pack2((w0.x - off) * ws, (w0.y - off) * ws);
        v.y = pack2((w1.x - off) * ws, (w1.y - off) * ws);
        *reinterpret_cast<uint2*>(g_Wb + (size_t)u * 128 + lane * 4) = v;
    };

    const int total = XTILES + WTILES;
    int t = gw * 2;
    const int stride = nw * 2;
    for (; t + 1 < total; t += stride) {
        if (t < XTILES) do_x(t); else do_w(t - XTILES);
        if (t + 1 < XTILES) do_x(t + 1); else do_w(t + 1 - XTILES);
    }
    if (t < total) {
        if (t < XTILES) do_x(t); else do_w(t - XTILES);
    }
}

// ---------------- persistent GEMM: mbarrier free-running 2-stage pipeline -----------
__global__ __launch_bounds__(THREADS, 1)
void gemm_persist(float* __restrict__ OUT) {
    extern __shared__ char smem[];
    const uint32_t sbase = smem_u32(smem);
    const uint32_t stg0 = sbase + SMEM_HDR;

    const int tid = threadIdx.x;
    const int wid = tid >> 5;       // 0..15
    const int lane = tid & 31;
    const int wm = wid >> 3;        // 0..1  (m half)
    const int wn = wid & 7;         // 0..7  (n eighth)

    if (tid == 0) {
        mbar_init(sbase + MB_FULL(0), THREADS);
        mbar_init(sbase + MB_FULL(1), THREADS);
        mbar_init(sbase + MB_EMPTY(0), THREADS);
        mbar_init(sbase + MB_EMPTY(1), THREADS);
    }
    __syncthreads();                 // only sync: after init

    auto tile_coords = [&](int tile, int& mb, int& nb) {
        const int grp = tile / (8 * NB);
        const int rem = tile - grp * (8 * NB);
        mb = grp * 8 + (rem & 7);
        nb = rem >> 3;
    };

    // issue this thread's slice of stage t into buffer buf; signal full[buf] on完成
    auto load_stage = [&](int buf, const __half* Ag, const __half* Bg, int t) {
        const uint32_t st = stg0 + buf * STAGE_BYTES;
        #pragma unroll
        for (int h = 0; h < 4; h++) {
            const char* a = (const char*)(Ag + (size_t)(4 * t + h) * A_HALVES) + tid * 16;
            cp16(st + h * A_KT_BYTES + tid * 16, a);
            const char* b = (const char*)(Bg + (size_t)(4 * t + h) * B_HALVES) + tid * 32;
            const uint32_t sb2 = st + STAGE_A_BYTES + h * B_KT_BYTES + tid * 32;
            cp16(sb2, b);
            cp16(sb2 + 16, b + 16);
        }
        cp_mbar_arrive(sbase + MB_FULL(buf));
    };

    float acc[4][4][4];

    auto compute = [&](int buf) {
        const char* stg = smem + SMEM_HDR + buf * STAGE_BYTES;
        #pragma unroll
        for (int h = 0; h < 4; h++) {
            const char* As = stg + h * A_KT_BYTES;
            const char* Bs = stg + STAGE_A_BYTES + h * B_KT_BYTES;
            #pragma unroll
            for (int kt2 = 0; kt2 < 2; kt2++) {
                uint4 af[4];
                #pragma unroll
                for (int mi = 0; mi < 4; mi++) {
                    const int mt = wm * 4 + mi;
                    af[mi] = *reinterpret_cast<const uint4*>(
                        As + (kt2 * 8 + mt) * 512 + lane * 16);
                }
                uint2 bf[4];
                #pragma unroll
                for (int ni = 0; ni < 4; ni++) {
                    const int nt = wn * 4 + ni;
                    bf[ni] = *reinterpret_cast<const uint2*>(
                        Bs + (kt2 * 32 + nt) * 256 + lane * 8);
                }
                #pragma unroll
                for (int mi = 0; mi < 4; mi++)
                    #pragma unroll
                    for (int ni = 0; ni < 4; ni++)
                        mma_f16(acc[mi][ni],
                                reinterpret_cast<const uint32_t*>(&af[mi]),
                                reinterpret_cast<const uint32_t*>(&bf[ni]));
            }
        }
    };

    int tile = blockIdx.x;
    if (tile >= NTILES) return;

    int mb, nb;
    tile_coords(tile, mb, nb);
    const __half* Ag = g_Xa + (size_t)mb * 128 * A_HALVES;
    const __half* Bg = g_Wb + (size_t)nb * 128 * B_HALVES;
    const __half* AgN = Ag;
    const __half* BgN = Bg;
    int mbN = mb, nbN = nb;

    // prologue: stage 0 into buf 0 (empty[0] trivially available)
    load_stage(0, Ag, Bg, 0);

    while (true) {
        #pragma unroll
        for (int i = 0; i < 4; i++)
            #pragma unroll
            for (int j = 0; j < 4; j++)
                #pragma unroll
                for (int c = 0; c < 4; c++) acc[i][j][c] = 0.f;

        #pragma unroll 1
        for (int t = 0; t < KP; t++) {
            // ---- producer: stage t+1 (or next tile's stage 0) ----
            // parity derivations: buffer flips 16x per tile (even) so parities
            // are pure functions of t; producer empty-parity = (((t+1)>>1)+1)&1,
            // consumer full-parity = (t>>1)&1. Verified across tile seams.
            if (t + 1 < KP) {
                const int bufn = (t + 1) & 1;
                mbar_wait(sbase + MB_EMPTY(bufn), (((t + 1) >> 1) + 1) & 1);
                load_stage(bufn, Ag, Bg, t + 1);
            } else {
                const int ntile = tile + GRID;
                if (ntile < NTILES) {
                    tile_coords(ntile, mbN, nbN);
                    AgN = g_Xa + (size_t)mbN * 128 * A_HALVES;
                    BgN = g_Wb + (size_t)nbN * 128 * B_HALVES;
                    mbar_wait(sbase + MB_EMPTY(0), 1);   // (((32)>>1)+1)&1 = 1
                    load_stage(0, AgN, BgN, 0);          // cross-tile prefetch
                }
            }
            // ---- consumer: stage t ----
            const int buf = t & 1;
            mbar_wait(sbase + MB_FULL(buf), (t >> 1) & 1);
            compute(buf);
            mbar_arrive(sbase + MB_EMPTY(buf));
        }

        // epilogue: overlaps in-flight cross-tile prefetch
        const int m0 = mb * BM + wm * 64;
        const int n0 = nb * BN + wn * 32;
        #pragma unroll
        for (int mi = 0; mi < 4; mi++) {
            const int row = m0 + mi * 16 + (lane >> 2);
            #pragma unroll
            for (int ni = 0; ni < 4; ni++) {
                const int col = n0 + ni * 8 + (lane & 3) * 2;
                float2 v0, v1;
                v0.x = acc[mi][ni][0]; v0.y = acc[mi][ni][1];
                v1.x = acc[mi][ni][2]; v1.y = acc[mi][ni][3];
                *reinterpret_cast<float2*>(OUT + (size_t)row * NN + col)       = v0;
                *reinterpret_cast<float2*>(OUT + (size_t)(row + 8) * NN + col) = v1;
            }
        }

        tile += GRID;
        if (tile >= NTILES) break;
        mb = mbN; nb = nbN; Ag = AgN; Bg = BgN;
    }
}

// ---------------- launch ----------------
extern "C" void kernel_launch(void* const* d_in, const int* in_sizes, int n_in,
                              void* d_out, int out_size) {
    const float* X   = (const float*)d_in[0];
    const float* SX  = (const float*)d_in[1];
    const float* W   = (const float*)d_in[2];
    const float* WS  = (const float*)d_in[3];
    const float* OFF = (const float*)d_in[4];
    float* OUT = (float*)d_out;

    cudaFuncSetAttribute(gemm_persist,
                         cudaFuncAttributeMaxDynamicSharedMemorySize, SMEM_TOTAL);

    prep_all<<<2048, 256>>>(X, SX, W, WS, OFF);

    gemm_persist<<<GRID, THREADS, SMEM_TOTAL>>>(OUT);
}